// round 2
// baseline (speedup 1.0000x reference)
#include <cuda_runtime.h>
#include <math.h>

#define BB 2
#define CC 3
#define HF 1080
#define WF 1920
#define HH 540
#define WH 960

// Scratch (static device globals — no allocations allowed)
__device__ float  g_luma [BB*HH*WH];   // half-res luma
__device__ float  g_edge [BB*HH*WH];   // edge magnitude (pre-blur)
__device__ float  g_blur [BB*HH*WH];   // blurred edge
__device__ float2 g_gradh[BB*HH*WH];   // half-res gradient field (x,y)

// Bilinear sample with border clamp (pixel coords)
__device__ __forceinline__ float bsample(const float* __restrict__ p,
                                         float y, float x, int H, int W) {
    y = fminf(fmaxf(y, 0.f), (float)(H - 1));
    x = fminf(fmaxf(x, 0.f), (float)(W - 1));
    int y0 = (int)floorf(y), x0 = (int)floorf(x);
    int y1 = min(y0 + 1, H - 1), x1 = min(x0 + 1, W - 1);
    float wy = y - (float)y0, wx = x - (float)x0;
    float v00 = p[y0 * W + x0], v01 = p[y0 * W + x1];
    float v10 = p[y1 * W + x0], v11 = p[y1 * W + x1];
    return (v00 * (1.f - wx) + v01 * wx) * (1.f - wy)
         + (v10 * (1.f - wx) + v11 * wx) * wy;
}

// ---------------------------------------------------------------------------
// Kernel 1: luma + bilinear downsample to 540x960 (align_corners)
// ---------------------------------------------------------------------------
__global__ void k_luma_down(const float* __restrict__ img) {
    int j = blockIdx.x * blockDim.x + threadIdx.x;
    int i = blockIdx.y;
    int b = blockIdx.z;
    if (j >= WH) return;

    float y = (float)i * ((float)(HF - 1) / (float)(HH - 1));
    float x = (float)j * ((float)(WF - 1) / (float)(WH - 1));
    y = fminf(fmaxf(y, 0.f), (float)(HF - 1));
    x = fminf(fmaxf(x, 0.f), (float)(WF - 1));
    int y0 = (int)floorf(y), x0 = (int)floorf(x);
    int y1 = min(y0 + 1, HF - 1), x1 = min(x0 + 1, WF - 1);
    float wy = y - (float)y0, wx = x - (float)x0;

    const float* r  = img + (size_t)b * CC * HF * WF;
    const float* g  = r + (size_t)HF * WF;
    const float* bl = g + (size_t)HF * WF;

    #define LUMA(yy, xx) (0.299f * r[(yy) * WF + (xx)] + 0.587f * g[(yy) * WF + (xx)] + 0.114f * bl[(yy) * WF + (xx)])
    float v00 = LUMA(y0, x0), v01 = LUMA(y0, x1);
    float v10 = LUMA(y1, x0), v11 = LUMA(y1, x1);
    #undef LUMA

    float v = (v00 * (1.f - wx) + v01 * wx) * (1.f - wy)
            + (v10 * (1.f - wx) + v11 * wx) * wy;
    g_luma[((size_t)b * HH + i) * WH + j] = v;
}

// ---------------------------------------------------------------------------
// Kernel 2: fused sobel_x(offset=1) + sobel_y(offset=1, magnitude=True)
// ---------------------------------------------------------------------------
__global__ void k_edge_mag() {
    int j = blockIdx.x * blockDim.x + threadIdx.x;
    int i = blockIdx.y;
    int b = blockIdx.z;
    if (j >= WH) return;

    const float* L = g_luma + (size_t)b * HH * WH;
    const float sx = (float)(WH - 1) / (float)WH;  // offset=1 pixel shift
    const float sy = (float)(HH - 1) / (float)HH;
    float fi = (float)i, fj = (float)j;
    float xm = fj - sx, xp = fj + sx;
    float ym = fi - sy, yp = fi + sy;

    float a_mm = bsample(L, ym, xm, HH, WH);
    float a_mc = bsample(L, ym, fj, HH, WH);
    float a_mp = bsample(L, ym, xp, HH, WH);
    float a_cm = bsample(L, fi, xm, HH, WH);
    float a_cp = bsample(L, fi, xp, HH, WH);
    float a_pm = bsample(L, yp, xm, HH, WH);
    float a_pc = bsample(L, yp, fj, HH, WH);
    float a_pp = bsample(L, yp, xp, HH, WH);

    float top0 = -a_mm + a_mp;
    float c0   = -a_cm + a_cp;
    float bot0 = -a_pm + a_pp;
    float top1 = a_mm + 2.f * a_mc + a_mp;
    float bot1 = a_pm + 2.f * a_pc + a_pp;

    float xg = (top0 + 2.f * c0 + bot0) * 0.125f;
    float yg = (bot1 - top1) * 0.125f;
    float mag = sqrtf(xg * xg + yg * yg);
    // mag^0.7 via fast exp2/log2 (exact enough: ~1e-6 rel; log2(0)->-inf->0 ok)
    g_edge[((size_t)b * HH + i) * WH + j] = exp2f(0.7f * __log2f(mag));
}

// ---------------------------------------------------------------------------
// Kernel 3: fused separable 5-tap gaussian (sigma=1), replicate pad, tiled
// ---------------------------------------------------------------------------
__constant__ float c_gw[3] = {0.40261995f, 0.24420135f, 0.05448868f};

__global__ void k_blur_fused() {
    __shared__ float sin_[36][37];
    __shared__ float shb[36][33];
    int bx = blockIdx.x * 32, by = blockIdx.y * 32, b = blockIdx.z;
    const float* E = g_edge + (size_t)b * HH * WH;
    int tid = threadIdx.x;

    for (int idx = tid; idx < 36 * 36; idx += 256) {
        int r = idx / 36, c = idx % 36;
        int gr = min(max(by - 2 + r, 0), HH - 1);
        int gc = min(max(bx - 2 + c, 0), WH - 1);
        sin_[r][c] = E[gr * WH + gc];
    }
    __syncthreads();
    for (int idx = tid; idx < 36 * 32; idx += 256) {
        int r = idx >> 5, c = idx & 31;
        shb[r][c] = c_gw[0] * sin_[r][c + 2]
                  + c_gw[1] * (sin_[r][c + 1] + sin_[r][c + 3])
                  + c_gw[2] * (sin_[r][c]     + sin_[r][c + 4]);
    }
    __syncthreads();
    for (int idx = tid; idx < 32 * 32; idx += 256) {
        int r = idx >> 5, c = idx & 31;
        int gr = by + r, gc = bx + c;
        if (gr < HH && gc < WH) {
            g_blur[((size_t)b * HH + gr) * WH + gc] =
                  c_gw[0] * shb[r + 2][c]
                + c_gw[1] * (shb[r + 1][c] + shb[r + 3][c])
                + c_gw[2] * (shb[r][c]     + shb[r + 4][c]);
        }
    }
}

// ---------------------------------------------------------------------------
// Kernel 4: fused sobel_x(0.5) + sobel_y(0.5, magnitude=False) -> float2 field
// ---------------------------------------------------------------------------
__global__ void k_grad_field() {
    int j = blockIdx.x * blockDim.x + threadIdx.x;
    int i = blockIdx.y;
    int b = blockIdx.z;
    if (j >= WH) return;

    const float* E = g_blur + (size_t)b * HH * WH;
    const float sx = 0.5f * (float)(WH - 1) / (float)WH;
    const float sy = 0.5f * (float)(HH - 1) / (float)HH;
    float fi = (float)i, fj = (float)j;
    float xm = fj - sx, xp = fj + sx;
    float ym = fi - sy, yp = fi + sy;

    float a_mm = bsample(E, ym, xm, HH, WH);
    float a_mc = bsample(E, ym, fj, HH, WH);
    float a_mp = bsample(E, ym, xp, HH, WH);
    float a_cm = bsample(E, fi, xm, HH, WH);
    float a_cp = bsample(E, fi, xp, HH, WH);
    float a_pm = bsample(E, yp, xm, HH, WH);
    float a_pc = bsample(E, yp, fj, HH, WH);
    float a_pp = bsample(E, yp, xp, HH, WH);

    float top0 = -a_mm + a_mp;
    float c0   = -a_cm + a_cp;
    float bot0 = -a_pm + a_pp;
    float top1 = a_mm + 2.f * a_mc + a_mp;
    float bot1 = a_pm + 2.f * a_pc + a_pp;

    float2 gv;
    gv.x = (top0 + 2.f * c0 + bot0) * 0.125f;
    gv.y = (bot1 - top1) * 0.125f;
    g_gradh[((size_t)b * HH + i) * WH + j] = gv;
}

// ---------------------------------------------------------------------------
// Kernel 5: warp loop sampling the (virtual) full-res field EXACTLY from the
// half-res field. F = bilinear-upsample(G); grid_sample(F, p) is a tensor-
// product of two 1D 3-tap evaluations of G (each 1D lerp of F spans <= 3
// half-res columns). Then final image sample + clip.
// ---------------------------------------------------------------------------
struct W3 { int k0; float w0, w1, w2; };

__device__ __forceinline__ W3 wcalc(float p, float r, int nfull, int nhalf) {
    // p in [0, nfull-1]; returns 3 weights over half-res cols k0..k0+2
    int j0 = (int)floorf(p);
    float t = p - (float)j0;
    int j1 = min(j0 + 1, nfull - 1);
    float u0 = (float)j0 * r;
    float u1 = (float)j1 * r;
    int k0 = min((int)floorf(u0), nhalf - 1);
    int k1 = min((int)floorf(u1), nhalf - 1);
    float a0 = u0 - (float)k0;
    float a1 = u1 - (float)k1;
    W3 w; w.k0 = k0;
    w.w0 = (1.f - t) * (1.f - a0);
    w.w1 = (1.f - t) * a0;
    w.w2 = 0.f;
    if (k1 == k0) { w.w0 += t * (1.f - a1); w.w1 += t * a1; }
    else          { w.w1 += t * (1.f - a1); w.w2 += t * a1; }
    return w;
}

__global__ void k_warp_fused(const float* __restrict__ img, float* __restrict__ out) {
    int j = blockIdx.x * blockDim.x + threadIdx.x;
    int i = blockIdx.y;
    int b = blockIdx.z;
    if (j >= WF) return;

    const float2* __restrict__ G = g_gradh + (size_t)b * HH * WH;
    const float RX = (float)(WH - 1) / (float)(WF - 1);
    const float RY = (float)(HH - 1) / (float)(HF - 1);
    // step in full-res pixel units: (2/W * 0.1) * (W-1)/2
    const float stepx = 0.1f * (float)(WF - 1) / (float)WF;
    const float stepy = 0.1f * (float)(HF - 1) / (float)HF;

    float px = (float)j, py = (float)i;   // unclamped position (pixel coords)

    #pragma unroll
    for (int it = 0; it < 6; ++it) {
        float cx = fminf(fmaxf(px, 0.f), (float)(WF - 1));
        float cy = fminf(fmaxf(py, 0.f), (float)(HF - 1));
        W3 wx = wcalc(cx, RX, WF, WH);
        W3 wy = wcalc(cy, RY, HF, HH);
        int c0 = wx.k0, c1 = min(c0 + 1, WH - 1), c2 = min(c0 + 2, WH - 1);
        int r0 = wy.k0, r1 = min(r0 + 1, HH - 1), r2 = min(r0 + 2, HH - 1);

        const float2* rp0 = G + (size_t)r0 * WH;
        const float2* rp1 = G + (size_t)r1 * WH;
        const float2* rp2 = G + (size_t)r2 * WH;
        float2 t00 = rp0[c0], t01 = rp0[c1], t02 = rp0[c2];
        float2 t10 = rp1[c0], t11 = rp1[c1], t12 = rp1[c2];
        float2 t20 = rp2[c0], t21 = rp2[c1], t22 = rp2[c2];

        float dx = wy.w0 * (wx.w0 * t00.x + wx.w1 * t01.x + wx.w2 * t02.x)
                 + wy.w1 * (wx.w0 * t10.x + wx.w1 * t11.x + wx.w2 * t12.x)
                 + wy.w2 * (wx.w0 * t20.x + wx.w1 * t21.x + wx.w2 * t22.x);
        float dy = wy.w0 * (wx.w0 * t00.y + wx.w1 * t01.y + wx.w2 * t02.y)
                 + wy.w1 * (wx.w0 * t10.y + wx.w1 * t11.y + wx.w2 * t12.y)
                 + wy.w2 * (wx.w0 * t20.y + wx.w1 * t21.y + wx.w2 * t22.y);

        float len = sqrtf(dx * dx + dy * dy) + 0.01f;
        float inv = 1.f / len;
        px -= dx * inv * stepx;
        py -= dy * inv * stepy;
    }

    // final image sample + clip
    float cx = fminf(fmaxf(px, 0.f), (float)(WF - 1));
    float cy = fminf(fmaxf(py, 0.f), (float)(HF - 1));
    int x0 = (int)floorf(cx), y0 = (int)floorf(cy);
    int x1 = min(x0 + 1, WF - 1), y1 = min(y0 + 1, HF - 1);
    float wx = cx - (float)x0, wy = cy - (float)y0;
    float w00 = (1.f - wx) * (1.f - wy), w01 = wx * (1.f - wy);
    float w10 = (1.f - wx) * wy,         w11 = wx * wy;

    const float* base  = img + (size_t)b * CC * HF * WF;
    float*       obase = out + (size_t)b * CC * HF * WF;
    #pragma unroll
    for (int c = 0; c < CC; ++c) {
        const float* p = base + (size_t)c * HF * WF;
        float v = w00 * p[y0 * WF + x0] + w01 * p[y0 * WF + x1]
                + w10 * p[y1 * WF + x0] + w11 * p[y1 * WF + x1];
        obase[(size_t)c * HF * WF + (size_t)i * WF + j] = fminf(fmaxf(v, 0.f), 1.f);
    }
}

// ---------------------------------------------------------------------------
extern "C" void kernel_launch(void* const* d_in, const int* in_sizes, int n_in,
                              void* d_out, int out_size) {
    const float* img = (const float*)d_in[0];
    float* out = (float*)d_out;

    dim3 blk_h(128);
    dim3 grid_h((WH + 127) / 128, HH, BB);
    dim3 blk_f(256);
    dim3 grid_f((WF + 255) / 256, HF, BB);
    dim3 grid_blur((WH + 31) / 32, (HH + 31) / 32, BB);

    k_luma_down <<<grid_h, blk_h>>>(img);
    k_edge_mag  <<<grid_h, blk_h>>>();
    k_blur_fused<<<grid_blur, 256>>>();
    k_grad_field<<<grid_h, blk_h>>>();
    k_warp_fused<<<grid_f, blk_f>>>(img, out);
}

// round 3
// speedup vs baseline: 1.6610x; 1.6610x over previous
#include <cuda_runtime.h>
#include <math.h>

#define BB 2
#define CC 3
#define HF 1080
#define WF 1920
#define HH 540
#define WH 960

// Constant fractional-shift weights (exact algebra of the reference's
// shift_sample at constant offset, incl. border clamp equivalence)
#define S1X (959.0f/960.0f)          // sobel offset=1, x shift (pixels)
#define S1Y (539.0f/540.0f)          // sobel offset=1, y shift
#define S2X (479.5f/960.0f)          // kernel offset=0.5, x shift
#define S2Y (269.5f/540.0f)          // kernel offset=0.5, y shift

// Scratch (static device globals — no allocations allowed)
__device__ float  g_luma [BB*HH*WH];
__device__ float  g_edge [BB*HH*WH];
__device__ float  g_blur [BB*HH*WH];
__device__ float2 g_gradh[BB*HH*WH];
__device__ float2 g_gradf[BB*HF*WF];

// ---------------------------------------------------------------------------
// Kernel 1: luma + bilinear downsample to 540x960 (align_corners)
// ---------------------------------------------------------------------------
__global__ void k_luma_down(const float* __restrict__ img) {
    int j = blockIdx.x * blockDim.x + threadIdx.x;
    int i = blockIdx.y;
    int b = blockIdx.z;
    if (j >= WH) return;

    float y = (float)i * ((float)(HF - 1) / (float)(HH - 1));
    float x = (float)j * ((float)(WF - 1) / (float)(WH - 1));
    y = fminf(y, (float)(HF - 1));
    x = fminf(x, (float)(WF - 1));
    int y0 = (int)y, x0 = (int)x;
    int y1 = min(y0 + 1, HF - 1), x1 = min(x0 + 1, WF - 1);
    float wy = y - (float)y0, wx = x - (float)x0;

    const float* r  = img + (size_t)b * CC * HF * WF;
    const float* g  = r + (size_t)HF * WF;
    const float* bl = g + (size_t)HF * WF;

    #define LUMA(yy, xx) (0.299f * r[(yy) * WF + (xx)] + 0.587f * g[(yy) * WF + (xx)] + 0.114f * bl[(yy) * WF + (xx)])
    float v00 = LUMA(y0, x0), v01 = LUMA(y0, x1);
    float v10 = LUMA(y1, x0), v11 = LUMA(y1, x1);
    #undef LUMA

    float v = (v00 * (1.f - wx) + v01 * wx) * (1.f - wy)
            + (v10 * (1.f - wx) + v11 * wx) * wy;
    g_luma[((size_t)b * HH + i) * WH + j] = v;
}

// ---------------------------------------------------------------------------
// Kernel 2: edge magnitude = constant-weight separable 3x3 stencil of luma
// ---------------------------------------------------------------------------
__global__ void k_edge_mag() {
    __shared__ float lum[34][35];
    __shared__ float c0s[34][33];
    __shared__ float c1s[34][33];
    int bx = blockIdx.x * 32, by = blockIdx.y * 32, b = blockIdx.z;
    const float* L = g_luma + (size_t)b * HH * WH;
    int tid = threadIdx.x;

    for (int idx = tid; idx < 34 * 34; idx += 256) {
        int r = idx / 34, c = idx % 34;
        int gr = min(max(by - 1 + r, 0), HH - 1);
        int gc = min(max(bx - 1 + c, 0), WH - 1);
        lum[r][c] = L[gr * WH + gc];
    }
    __syncthreads();
    for (int idx = tid; idx < 34 * 32; idx += 256) {
        int r = idx >> 5, c = idx & 31;
        float lf = lum[r][c], ce = lum[r][c + 1], ri = lum[r][c + 2];
        c0s[r][c] = S1X * (ri - lf);
        c1s[r][c] = S1X * (lf + ri) + (4.f - 2.f * S1X) * ce;
    }
    __syncthreads();
    for (int idx = tid; idx < 32 * 32; idx += 256) {
        int r = idx >> 5, c = idx & 31;
        int gr = by + r, gc = bx + c;
        if (gr < HH && gc < WH) {
            float xg = (S1Y * (c0s[r][c] + c0s[r + 2][c])
                        + (4.f - 2.f * S1Y) * c0s[r + 1][c]) * 0.125f;
            float yg = S1Y * (c1s[r + 2][c] - c1s[r][c]) * 0.125f;
            float mag = sqrtf(xg * xg + yg * yg);
            g_edge[((size_t)b * HH + gr) * WH + gc] = exp2f(0.7f * __log2f(mag));
        }
    }
}

// ---------------------------------------------------------------------------
// Kernel 3: fused separable 5-tap gaussian (sigma=1), replicate pad, tiled
// ---------------------------------------------------------------------------
__constant__ float c_gw[3] = {0.40261995f, 0.24420135f, 0.05448868f};

__global__ void k_blur_fused() {
    __shared__ float sin_[36][37];
    __shared__ float shb[36][33];
    int bx = blockIdx.x * 32, by = blockIdx.y * 32, b = blockIdx.z;
    const float* E = g_edge + (size_t)b * HH * WH;
    int tid = threadIdx.x;

    for (int idx = tid; idx < 36 * 36; idx += 256) {
        int r = idx / 36, c = idx % 36;
        int gr = min(max(by - 2 + r, 0), HH - 1);
        int gc = min(max(bx - 2 + c, 0), WH - 1);
        sin_[r][c] = E[gr * WH + gc];
    }
    __syncthreads();
    for (int idx = tid; idx < 36 * 32; idx += 256) {
        int r = idx >> 5, c = idx & 31;
        shb[r][c] = c_gw[0] * sin_[r][c + 2]
                  + c_gw[1] * (sin_[r][c + 1] + sin_[r][c + 3])
                  + c_gw[2] * (sin_[r][c]     + sin_[r][c + 4]);
    }
    __syncthreads();
    for (int idx = tid; idx < 32 * 32; idx += 256) {
        int r = idx >> 5, c = idx & 31;
        int gr = by + r, gc = bx + c;
        if (gr < HH && gc < WH) {
            g_blur[((size_t)b * HH + gr) * WH + gc] =
                  c_gw[0] * shb[r + 2][c]
                + c_gw[1] * (shb[r + 1][c] + shb[r + 3][c])
                + c_gw[2] * (shb[r][c]     + shb[r + 4][c]);
        }
    }
}

// ---------------------------------------------------------------------------
// Kernel 4: gradient field = constant-weight separable 3x3 stencil of blur
// ---------------------------------------------------------------------------
__global__ void k_grad_field() {
    __shared__ float blr[34][35];
    __shared__ float c0s[34][33];
    __shared__ float c1s[34][33];
    int bx = blockIdx.x * 32, by = blockIdx.y * 32, b = blockIdx.z;
    const float* E = g_blur + (size_t)b * HH * WH;
    int tid = threadIdx.x;

    for (int idx = tid; idx < 34 * 34; idx += 256) {
        int r = idx / 34, c = idx % 34;
        int gr = min(max(by - 1 + r, 0), HH - 1);
        int gc = min(max(bx - 1 + c, 0), WH - 1);
        blr[r][c] = E[gr * WH + gc];
    }
    __syncthreads();
    for (int idx = tid; idx < 34 * 32; idx += 256) {
        int r = idx >> 5, c = idx & 31;
        float lf = blr[r][c], ce = blr[r][c + 1], ri = blr[r][c + 2];
        c0s[r][c] = S2X * (ri - lf);
        c1s[r][c] = S2X * (lf + ri) + (4.f - 2.f * S2X) * ce;
    }
    __syncthreads();
    for (int idx = tid; idx < 32 * 32; idx += 256) {
        int r = idx >> 5, c = idx & 31;
        int gr = by + r, gc = bx + c;
        if (gr < HH && gc < WH) {
            float2 gv;
            gv.x = (S2Y * (c0s[r][c] + c0s[r + 2][c])
                    + (4.f - 2.f * S2Y) * c0s[r + 1][c]) * 0.125f;
            gv.y = S2Y * (c1s[r + 2][c] - c1s[r][c]) * 0.125f;
            g_gradh[((size_t)b * HH + gr) * WH + gc] = gv;
        }
    }
}

// ---------------------------------------------------------------------------
// Kernel 5: bilinear upsample gradient field to full res (align_corners)
// ---------------------------------------------------------------------------
__global__ void k_upsample() {
    int j = blockIdx.x * blockDim.x + threadIdx.x;
    int i = blockIdx.y;
    int b = blockIdx.z;
    if (j >= WF) return;

    float y = (float)i * ((float)(HH - 1) / (float)(HF - 1));
    float x = (float)j * ((float)(WH - 1) / (float)(WF - 1));
    y = fminf(y, (float)(HH - 1));
    x = fminf(x, (float)(WH - 1));
    int y0 = (int)y, x0 = (int)x;
    int y1 = min(y0 + 1, HH - 1), x1 = min(x0 + 1, WH - 1);
    float wy = y - (float)y0, wx = x - (float)x0;

    const float2* __restrict__ G = g_gradh + (size_t)b * HH * WH;
    float2 v00 = G[y0 * WH + x0], v01 = G[y0 * WH + x1];
    float2 v10 = G[y1 * WH + x0], v11 = G[y1 * WH + x1];

    float2 v;
    v.x = (v00.x * (1.f - wx) + v01.x * wx) * (1.f - wy)
        + (v10.x * (1.f - wx) + v11.x * wx) * wy;
    v.y = (v00.y * (1.f - wx) + v01.y * wx) * (1.f - wy)
        + (v10.y * (1.f - wx) + v11.y * wx) * wy;
    g_gradf[((size_t)b * HF + i) * WF + j] = v;
}

// ---------------------------------------------------------------------------
// Kernel 6: warp loop (2 rows per thread for ILP) + final sample + clip
// ---------------------------------------------------------------------------
__global__ void __launch_bounds__(256) k_warp(const float* __restrict__ img,
                                              float* __restrict__ out) {
    int j = blockIdx.x * blockDim.x + threadIdx.x;
    int i0 = blockIdx.y * 2;
    int b = blockIdx.z;
    if (j >= WF) return;

    const float2* __restrict__ G = g_gradf + (size_t)b * HF * WF;
    const float stepx = 0.1f * (float)(WF - 1) / (float)WF;  // px units
    const float stepy = 0.1f * (float)(HF - 1) / (float)HF;

    float px[2], py[2];
    px[0] = (float)j; py[0] = (float)i0;
    px[1] = (float)j; py[1] = (float)(i0 + 1);

    #pragma unroll
    for (int it = 0; it < 6; ++it) {
        float dx[2], dy[2];
        #pragma unroll
        for (int s = 0; s < 2; ++s) {
            float cx = fminf(fmaxf(px[s], 0.f), (float)(WF - 1));
            float cy = fminf(fmaxf(py[s], 0.f), (float)(HF - 1));
            int x0 = (int)cx, y0 = (int)cy;
            int x1 = min(x0 + 1, WF - 1), y1 = min(y0 + 1, HF - 1);
            float wx = cx - (float)x0, wy = cy - (float)y0;
            float2 v00 = G[y0 * WF + x0], v01 = G[y0 * WF + x1];
            float2 v10 = G[y1 * WF + x0], v11 = G[y1 * WF + x1];
            dx[s] = (v00.x * (1.f - wx) + v01.x * wx) * (1.f - wy)
                  + (v10.x * (1.f - wx) + v11.x * wx) * wy;
            dy[s] = (v00.y * (1.f - wx) + v01.y * wx) * (1.f - wy)
                  + (v10.y * (1.f - wx) + v11.y * wx) * wy;
        }
        #pragma unroll
        for (int s = 0; s < 2; ++s) {
            float len = sqrtf(dx[s] * dx[s] + dy[s] * dy[s]) + 0.01f;
            float inv = __fdividef(1.f, len);
            px[s] -= dx[s] * inv * stepx;
            py[s] -= dy[s] * inv * stepy;
        }
    }

    const float* base  = img + (size_t)b * CC * HF * WF;
    float*       obase = out + (size_t)b * CC * HF * WF;

    #pragma unroll
    for (int s = 0; s < 2; ++s) {
        float cx = fminf(fmaxf(px[s], 0.f), (float)(WF - 1));
        float cy = fminf(fmaxf(py[s], 0.f), (float)(HF - 1));
        int x0 = (int)cx, y0 = (int)cy;
        int x1 = min(x0 + 1, WF - 1), y1 = min(y0 + 1, HF - 1);
        float wx = cx - (float)x0, wy = cy - (float)y0;
        float w00 = (1.f - wx) * (1.f - wy), w01 = wx * (1.f - wy);
        float w10 = (1.f - wx) * wy,         w11 = wx * wy;
        int i = i0 + s;
        #pragma unroll
        for (int c = 0; c < CC; ++c) {
            const float* p = base + (size_t)c * HF * WF;
            float v = w00 * p[y0 * WF + x0] + w01 * p[y0 * WF + x1]
                    + w10 * p[y1 * WF + x0] + w11 * p[y1 * WF + x1];
            obase[(size_t)c * HF * WF + (size_t)i * WF + j] = fminf(fmaxf(v, 0.f), 1.f);
        }
    }
}

// ---------------------------------------------------------------------------
extern "C" void kernel_launch(void* const* d_in, const int* in_sizes, int n_in,
                              void* d_out, int out_size) {
    const float* img = (const float*)d_in[0];
    float* out = (float*)d_out;

    dim3 grid_h((WH + 255) / 256, HH, BB);
    dim3 grid_t((WH + 31) / 32, (HH + 31) / 32, BB);
    dim3 grid_f((WF + 255) / 256, HF, BB);
    dim3 grid_w((WF + 255) / 256, HF / 2, BB);

    k_luma_down <<<grid_h, 256>>>(img);
    k_edge_mag  <<<grid_t, 256>>>();
    k_blur_fused<<<grid_t, 256>>>();
    k_grad_field<<<grid_t, 256>>>();
    k_upsample  <<<grid_f, 256>>>();
    k_warp      <<<grid_w, 256>>>(img, out);
}

// round 4
// speedup vs baseline: 1.8995x; 1.1436x over previous
#include <cuda_runtime.h>
#include <math.h>

#define BB 2
#define CC 3
#define HF 1080
#define WF 1920
#define HH 540
#define WH 960

// Constant fractional-shift weights (exact algebra of reference shift_sample)
#define S1X (959.0f/960.0f)
#define S1Y (539.0f/540.0f)
#define S2X (479.5f/960.0f)
#define S2Y (269.5f/540.0f)

__device__ float  g_luma [BB*HH*WH];
__device__ float2 g_gradh[BB*HH*WH];

__constant__ float c_gw[3] = {0.40261995f, 0.24420135f, 0.05448868f};

// ---------------------------------------------------------------------------
// Kernel 1: luma + bilinear downsample to 540x960 (align_corners)
// ---------------------------------------------------------------------------
__global__ void k_luma_down(const float* __restrict__ img) {
    int j = blockIdx.x * blockDim.x + threadIdx.x;
    int i = blockIdx.y;
    int b = blockIdx.z;
    if (j >= WH) return;

    float y = fminf((float)i * ((float)(HF - 1) / (float)(HH - 1)), (float)(HF - 1));
    float x = fminf((float)j * ((float)(WF - 1) / (float)(WH - 1)), (float)(WF - 1));
    int y0 = (int)y, x0 = (int)x;
    int y1 = min(y0 + 1, HF - 1), x1 = min(x0 + 1, WF - 1);
    float wy = y - (float)y0, wx = x - (float)x0;

    const float* r  = img + (size_t)b * CC * HF * WF;
    const float* g  = r + (size_t)HF * WF;
    const float* bl = g + (size_t)HF * WF;

    #define LUMA(yy, xx) (0.299f * r[(yy) * WF + (xx)] + 0.587f * g[(yy) * WF + (xx)] + 0.114f * bl[(yy) * WF + (xx)])
    float v00 = LUMA(y0, x0), v01 = LUMA(y0, x1);
    float v10 = LUMA(y1, x0), v11 = LUMA(y1, x1);
    #undef LUMA

    float v = (v00 * (1.f - wx) + v01 * wx) * (1.f - wy)
            + (v10 * (1.f - wx) + v11 * wx) * wy;
    g_luma[((size_t)b * HH + i) * WH + j] = v;
}

// ---------------------------------------------------------------------------
// Kernel 2: FUSED edge-magnitude -> gaussian blur -> gradient field.
// 32x32 output tile, staged in shared memory with a 4-px halo.
// Clamp semantics: every stage reads its source at globally-clamped
// coordinates; halo entries outside the image are computed but never consumed.
// ---------------------------------------------------------------------------
__global__ void __launch_bounds__(256) k_field() {
    __shared__ float s_lum [40][41];   // luma,  origin (by0-4, bx0-4)
    __shared__ float s_edge[38][39];   // edge,  origin (by0-3, bx0-3)
    __shared__ float s_bh  [38][35];   // blur-h, rows as edge, cols origin bx0-1
    __shared__ float s_bv  [34][35];   // blur,  origin (by0-1, bx0-1)

    int bx0 = blockIdx.x * 32, by0 = blockIdx.y * 32, b = blockIdx.z;
    const float* __restrict__ L = g_luma + (size_t)b * HH * WH;
    int tid = threadIdx.x;

    // --- load luma 40x40 (clamped) ---
    for (int idx = tid; idx < 40 * 40; idx += 256) {
        int r = idx / 40, c = idx % 40;
        int gr = min(max(by0 - 4 + r, 0), HH - 1);
        int gc = min(max(bx0 - 4 + c, 0), WH - 1);
        s_lum[r][c] = L[gr * WH + gc];
    }
    __syncthreads();

    // --- edge magnitude 38x38 ---
    for (int idx = tid; idx < 38 * 38; idx += 256) {
        int r = idx / 38, c = idx % 38;
        int gr = by0 - 3 + r, gc = bx0 - 3 + c;
        int r0 = min(max(gr - 1, 0), HH - 1) - (by0 - 4);
        int r1 = min(max(gr,     0), HH - 1) - (by0 - 4);
        int r2 = min(max(gr + 1, 0), HH - 1) - (by0 - 4);
        int c0 = min(max(gc - 1, 0), WH - 1) - (bx0 - 4);
        int c1 = min(max(gc,     0), WH - 1) - (bx0 - 4);
        int c2 = min(max(gc + 1, 0), WH - 1) - (bx0 - 4);

        float a00 = s_lum[r0][c0], a01 = s_lum[r0][c1], a02 = s_lum[r0][c2];
        float a10 = s_lum[r1][c0], a11 = s_lum[r1][c1], a12 = s_lum[r1][c2];
        float a20 = s_lum[r2][c0], a21 = s_lum[r2][c1], a22 = s_lum[r2][c2];

        float ch0m = S1X * (a02 - a00);
        float ch0c = S1X * (a12 - a10);
        float ch0p = S1X * (a22 - a20);
        float ch1m = S1X * (a00 + a02) + (4.f - 2.f * S1X) * a01;
        float ch1p = S1X * (a20 + a22) + (4.f - 2.f * S1X) * a21;

        float xg = (S1Y * (ch0m + ch0p) + (4.f - 2.f * S1Y) * ch0c) * 0.125f;
        float yg = S1Y * (ch1p - ch1m) * 0.125f;
        float mag = sqrtf(xg * xg + yg * yg);
        s_edge[r][c] = exp2f(0.7f * __log2f(mag));
    }
    __syncthreads();

    // --- blur horizontal: 38 rows x 34 cols (cols global bx0-1+c) ---
    for (int idx = tid; idx < 38 * 34; idx += 256) {
        int r = idx / 34, c = idx % 34;
        int gc = bx0 - 1 + c;
        int l0 = min(max(gc - 2, 0), WH - 1) - (bx0 - 3);
        int l1 = min(max(gc - 1, 0), WH - 1) - (bx0 - 3);
        int l2 = min(max(gc,     0), WH - 1) - (bx0 - 3);
        int l3 = min(max(gc + 1, 0), WH - 1) - (bx0 - 3);
        int l4 = min(max(gc + 2, 0), WH - 1) - (bx0 - 3);
        s_bh[r][c] = c_gw[0] * s_edge[r][l2]
                   + c_gw[1] * (s_edge[r][l1] + s_edge[r][l3])
                   + c_gw[2] * (s_edge[r][l0] + s_edge[r][l4]);
    }
    __syncthreads();

    // --- blur vertical: 34x34 (rows global by0-1+r) ---
    for (int idx = tid; idx < 34 * 34; idx += 256) {
        int r = idx / 34, c = idx % 34;
        int gr = by0 - 1 + r;
        int l0 = min(max(gr - 2, 0), HH - 1) - (by0 - 3);
        int l1 = min(max(gr - 1, 0), HH - 1) - (by0 - 3);
        int l2 = min(max(gr,     0), HH - 1) - (by0 - 3);
        int l3 = min(max(gr + 1, 0), HH - 1) - (by0 - 3);
        int l4 = min(max(gr + 2, 0), HH - 1) - (by0 - 3);
        s_bv[r][c] = c_gw[0] * s_bh[l2][c]
                   + c_gw[1] * (s_bh[l1][c] + s_bh[l3][c])
                   + c_gw[2] * (s_bh[l0][c] + s_bh[l4][c]);
    }
    __syncthreads();

    // --- gradient field 32x32 -> g_gradh ---
    for (int idx = tid; idx < 32 * 32; idx += 256) {
        int r = idx >> 5, c = idx & 31;
        int gr = by0 + r, gc = bx0 + c;
        if (gr >= HH || gc >= WH) continue;
        int r0 = min(max(gr - 1, 0), HH - 1) - (by0 - 1);
        int r1 = gr - (by0 - 1);
        int r2 = min(gr + 1, HH - 1) - (by0 - 1);
        int c0 = min(max(gc - 1, 0), WH - 1) - (bx0 - 1);
        int c1 = gc - (bx0 - 1);
        int c2 = min(gc + 1, WH - 1) - (bx0 - 1);

        float a00 = s_bv[r0][c0], a01 = s_bv[r0][c1], a02 = s_bv[r0][c2];
        float a10 = s_bv[r1][c0], a11 = s_bv[r1][c1], a12 = s_bv[r1][c2];
        float a20 = s_bv[r2][c0], a21 = s_bv[r2][c1], a22 = s_bv[r2][c2];

        float ch0m = S2X * (a02 - a00);
        float ch0c = S2X * (a12 - a10);
        float ch0p = S2X * (a22 - a20);
        float ch1m = S2X * (a00 + a02) + (4.f - 2.f * S2X) * a01;
        float ch1p = S2X * (a20 + a22) + (4.f - 2.f * S2X) * a21;

        float2 gv;
        gv.x = (S2Y * (ch0m + ch0p) + (4.f - 2.f * S2Y) * ch0c) * 0.125f;
        gv.y = S2Y * (ch1p - ch1m) * 0.125f;
        g_gradh[((size_t)b * HH + gr) * WH + gc] = gv;
    }
}

// ---------------------------------------------------------------------------
// Kernel 3: warp. Positions move < 0.6 px total (6 iters x ~0.1 px), so a
// 32x8 block samples the virtual full-res field only inside a 34x10 window.
// Precompute those field values (exact bilinear upsample of g_gradh) into
// SMEM once, then run the 6-iteration loop entirely from SMEM.
// ---------------------------------------------------------------------------
__global__ void __launch_bounds__(256) k_warp(const float* __restrict__ img,
                                              float* __restrict__ out) {
    __shared__ float2 sF[10][35];
    int bx0 = blockIdx.x * 32, by0 = blockIdx.y * 8, b = blockIdx.z;
    int tid = threadIdx.y * 32 + threadIdx.x;

    const float2* __restrict__ G = g_gradh + (size_t)b * HH * WH;

    // Fill field tile: gx in [bx0-1, bx0+32], gy in [by0-1, by0+8] (clamped)
    for (int idx = tid; idx < 34 * 10; idx += 256) {
        int ly = idx / 34, lx = idx % 34;
        int gx = min(max(bx0 - 1 + lx, 0), WF - 1);
        int gy = min(max(by0 - 1 + ly, 0), HF - 1);
        float y = fminf((float)gy * ((float)(HH - 1) / (float)(HF - 1)), (float)(HH - 1));
        float x = fminf((float)gx * ((float)(WH - 1) / (float)(WF - 1)), (float)(WH - 1));
        int y0 = (int)y, x0 = (int)x;
        int y1 = min(y0 + 1, HH - 1), x1 = min(x0 + 1, WH - 1);
        float wy = y - (float)y0, wx = x - (float)x0;
        float2 v00 = __ldg(&G[y0 * WH + x0]), v01 = __ldg(&G[y0 * WH + x1]);
        float2 v10 = __ldg(&G[y1 * WH + x0]), v11 = __ldg(&G[y1 * WH + x1]);
        float2 v;
        v.x = (v00.x * (1.f - wx) + v01.x * wx) * (1.f - wy)
            + (v10.x * (1.f - wx) + v11.x * wx) * wy;
        v.y = (v00.y * (1.f - wx) + v01.y * wx) * (1.f - wy)
            + (v10.y * (1.f - wx) + v11.y * wx) * wy;
        sF[ly][lx] = v;
    }
    __syncthreads();

    int j = bx0 + threadIdx.x;
    int i = by0 + threadIdx.y;

    const float stepx = 0.1f * (float)(WF - 1) / (float)WF;  // pixel units
    const float stepy = 0.1f * (float)(HF - 1) / (float)HF;
    const float ox = (float)(bx0 - 1), oy = (float)(by0 - 1);

    float px = (float)j, py = (float)i;

    #pragma unroll
    for (int it = 0; it < 6; ++it) {
        float cx = fminf(fmaxf(px, 0.f), (float)(WF - 1));
        float cy = fminf(fmaxf(py, 0.f), (float)(HF - 1));
        float lx = cx - ox, ly = cy - oy;     // in [0.4, 32.6] x [0.4, 8.6]
        int x0 = (int)lx, y0 = (int)ly;
        float wx = lx - (float)x0, wy = ly - (float)y0;
        float2 v00 = sF[y0][x0],     v01 = sF[y0][x0 + 1];
        float2 v10 = sF[y0 + 1][x0], v11 = sF[y0 + 1][x0 + 1];
        float dx = (v00.x * (1.f - wx) + v01.x * wx) * (1.f - wy)
                 + (v10.x * (1.f - wx) + v11.x * wx) * wy;
        float dy = (v00.y * (1.f - wx) + v01.y * wx) * (1.f - wy)
                 + (v10.y * (1.f - wx) + v11.y * wx) * wy;
        float len = sqrtf(dx * dx + dy * dy) + 0.01f;
        float inv = __fdividef(1.f, len);
        px -= dx * inv * stepx;
        py -= dy * inv * stepy;
    }

    // final image sample + clip
    float cx = fminf(fmaxf(px, 0.f), (float)(WF - 1));
    float cy = fminf(fmaxf(py, 0.f), (float)(HF - 1));
    int x0 = (int)cx, y0 = (int)cy;
    int x1 = min(x0 + 1, WF - 1), y1 = min(y0 + 1, HF - 1);
    float wx = cx - (float)x0, wy = cy - (float)y0;
    float w00 = (1.f - wx) * (1.f - wy), w01 = wx * (1.f - wy);
    float w10 = (1.f - wx) * wy,         w11 = wx * wy;

    const float* base  = img + (size_t)b * CC * HF * WF;
    float*       obase = out + (size_t)b * CC * HF * WF;
    #pragma unroll
    for (int c = 0; c < CC; ++c) {
        const float* p = base + (size_t)c * HF * WF;
        float v = w00 * p[y0 * WF + x0] + w01 * p[y0 * WF + x1]
                + w10 * p[y1 * WF + x0] + w11 * p[y1 * WF + x1];
        obase[(size_t)c * HF * WF + (size_t)i * WF + j] = fminf(fmaxf(v, 0.f), 1.f);
    }
}

// ---------------------------------------------------------------------------
extern "C" void kernel_launch(void* const* d_in, const int* in_sizes, int n_in,
                              void* d_out, int out_size) {
    const float* img = (const float*)d_in[0];
    float* out = (float*)d_out;

    dim3 grid_l((WH + 255) / 256, HH, BB);
    dim3 grid_t((WH + 31) / 32, (HH + 31) / 32, BB);
    dim3 grid_w(WF / 32, HF / 8, BB);

    k_luma_down<<<grid_l, 256>>>(img);
    k_field    <<<grid_t, 256>>>();
    k_warp     <<<grid_w, dim3(32, 8)>>>(img, out);
}

// round 6
// speedup vs baseline: 2.0345x; 1.0711x over previous
#include <cuda_runtime.h>
#include <math.h>

#define BB 2
#define CC 3
#define HF 1080
#define WF 1920
#define HH 540
#define WH 960

#define S1X (959.0f/960.0f)
#define S1Y (539.0f/540.0f)
#define S2X (479.5f/960.0f)
#define S2Y (269.5f/540.0f)

__device__ float  g_luma [BB*HH*WH];
__device__ float2 g_gradh[BB*HH*WH];

__constant__ float c_gw[3] = {0.40261995f, 0.24420135f, 0.05448868f};

// ---------------------------------------------------------------------------
// Kernel 1: luma + bilinear downsample, 2 outputs per thread (MLP)
// ---------------------------------------------------------------------------
__global__ void k_luma_down(const float* __restrict__ img) {
    int j0 = (blockIdx.x * blockDim.x + threadIdx.x) * 2;
    int i = blockIdx.y;
    int b = blockIdx.z;
    if (j0 >= WH) return;

    float y = fminf((float)i * ((float)(HF - 1) / (float)(HH - 1)), (float)(HF - 1));
    int y0 = (int)y;
    int y1 = min(y0 + 1, HF - 1);
    float wy = y - (float)y0;

    const float* r  = img + (size_t)b * CC * HF * WF;
    const float* g  = r + (size_t)HF * WF;
    const float* bl = g + (size_t)HF * WF;

    #pragma unroll
    for (int s = 0; s < 2; ++s) {
        int j = j0 + s;
        if (j >= WH) break;
        float x = fminf((float)j * ((float)(WF - 1) / (float)(WH - 1)), (float)(WF - 1));
        int x0 = (int)x;
        int x1 = min(x0 + 1, WF - 1);
        float wx = x - (float)x0;

        #define LUMA(yy, xx) (0.299f * __ldg(&r[(yy) * WF + (xx)]) + 0.587f * __ldg(&g[(yy) * WF + (xx)]) + 0.114f * __ldg(&bl[(yy) * WF + (xx)]))
        float v00 = LUMA(y0, x0), v01 = LUMA(y0, x1);
        float v10 = LUMA(y1, x0), v11 = LUMA(y1, x1);
        #undef LUMA

        float v = (v00 * (1.f - wx) + v01 * wx) * (1.f - wy)
                + (v10 * (1.f - wx) + v11 * wx) * wy;
        g_luma[((size_t)b * HH + i) * WH + j] = v;
    }
}

// ---------------------------------------------------------------------------
// Kernel 2: FUSED edge -> blur -> gradient field, interior fast path
// ---------------------------------------------------------------------------
__global__ void __launch_bounds__(256) k_field() {
    __shared__ float s_lum [40][41];
    __shared__ float s_edge[38][39];
    __shared__ float s_bh  [38][35];
    __shared__ float s_bv  [34][35];

    int bx0 = blockIdx.x * 32, by0 = blockIdx.y * 32, b = blockIdx.z;
    const float* __restrict__ L = g_luma + (size_t)b * HH * WH;
    int tid = threadIdx.x;

    bool interior = (bx0 >= 4) && (by0 >= 4) && (bx0 + 35 <= WH - 1) && (by0 + 35 <= HH - 1);

    if (interior) {
        const float* Lb = L + (size_t)(by0 - 4) * WH + (bx0 - 4);
        for (int idx = tid; idx < 40 * 40; idx += 256) {
            int r = idx / 40, c = idx % 40;
            s_lum[r][c] = Lb[r * WH + c];
        }
        __syncthreads();

        for (int idx = tid; idx < 38 * 38; idx += 256) {
            int r = idx / 38, c = idx % 38;
            float a00 = s_lum[r][c],     a01 = s_lum[r][c + 1],     a02 = s_lum[r][c + 2];
            float a10 = s_lum[r + 1][c], a12 = s_lum[r + 1][c + 2];
            float a20 = s_lum[r + 2][c], a21 = s_lum[r + 2][c + 1], a22 = s_lum[r + 2][c + 2];
            float ch0m = S1X * (a02 - a00);
            float ch0c = S1X * (a12 - a10);
            float ch0p = S1X * (a22 - a20);
            float ch1m = S1X * (a00 + a02) + (4.f - 2.f * S1X) * a01;
            float ch1p = S1X * (a20 + a22) + (4.f - 2.f * S1X) * a21;
            float xg = (S1Y * (ch0m + ch0p) + (4.f - 2.f * S1Y) * ch0c) * 0.125f;
            float yg = S1Y * (ch1p - ch1m) * 0.125f;
            float mag = sqrtf(xg * xg + yg * yg);
            s_edge[r][c] = exp2f(0.7f * __log2f(mag));
        }
        __syncthreads();

        for (int idx = tid; idx < 38 * 34; idx += 256) {
            int r = idx / 34, c = idx % 34;
            s_bh[r][c] = c_gw[0] * s_edge[r][c + 2]
                       + c_gw[1] * (s_edge[r][c + 1] + s_edge[r][c + 3])
                       + c_gw[2] * (s_edge[r][c]     + s_edge[r][c + 4]);
        }
        __syncthreads();

        for (int idx = tid; idx < 34 * 34; idx += 256) {
            int r = idx / 34, c = idx % 34;
            s_bv[r][c] = c_gw[0] * s_bh[r + 2][c]
                       + c_gw[1] * (s_bh[r + 1][c] + s_bh[r + 3][c])
                       + c_gw[2] * (s_bh[r][c]     + s_bh[r + 4][c]);
        }
        __syncthreads();

        for (int idx = tid; idx < 32 * 32; idx += 256) {
            int r = idx >> 5, c = idx & 31;
            float a00 = s_bv[r][c],     a01 = s_bv[r][c + 1],     a02 = s_bv[r][c + 2];
            float a10 = s_bv[r + 1][c], a12 = s_bv[r + 1][c + 2];
            float a20 = s_bv[r + 2][c], a21 = s_bv[r + 2][c + 1], a22 = s_bv[r + 2][c + 2];
            float ch0m = S2X * (a02 - a00);
            float ch0c = S2X * (a12 - a10);
            float ch0p = S2X * (a22 - a20);
            float ch1m = S2X * (a00 + a02) + (4.f - 2.f * S2X) * a01;
            float ch1p = S2X * (a20 + a22) + (4.f - 2.f * S2X) * a21;
            float2 gv;
            gv.x = (S2Y * (ch0m + ch0p) + (4.f - 2.f * S2Y) * ch0c) * 0.125f;
            gv.y = S2Y * (ch1p - ch1m) * 0.125f;
            g_gradh[((size_t)b * HH + by0 + r) * WH + (bx0 + c)] = gv;
        }
        return;
    }

    // ----- border path (clamped) -----
    for (int idx = tid; idx < 40 * 40; idx += 256) {
        int r = idx / 40, c = idx % 40;
        int gr = min(max(by0 - 4 + r, 0), HH - 1);
        int gc = min(max(bx0 - 4 + c, 0), WH - 1);
        s_lum[r][c] = L[gr * WH + gc];
    }
    __syncthreads();

    for (int idx = tid; idx < 38 * 38; idx += 256) {
        int r = idx / 38, c = idx % 38;
        int gr = by0 - 3 + r, gc = bx0 - 3 + c;
        int r0 = min(max(gr - 1, 0), HH - 1) - (by0 - 4);
        int r1 = min(max(gr,     0), HH - 1) - (by0 - 4);
        int r2 = min(max(gr + 1, 0), HH - 1) - (by0 - 4);
        int c0 = min(max(gc - 1, 0), WH - 1) - (bx0 - 4);
        int c1 = min(max(gc,     0), WH - 1) - (bx0 - 4);
        int c2 = min(max(gc + 1, 0), WH - 1) - (bx0 - 4);
        float a00 = s_lum[r0][c0], a01 = s_lum[r0][c1], a02 = s_lum[r0][c2];
        float a10 = s_lum[r1][c0], a12 = s_lum[r1][c2];
        float a20 = s_lum[r2][c0], a21 = s_lum[r2][c1], a22 = s_lum[r2][c2];
        float ch0m = S1X * (a02 - a00);
        float ch0c = S1X * (a12 - a10);
        float ch0p = S1X * (a22 - a20);
        float ch1m = S1X * (a00 + a02) + (4.f - 2.f * S1X) * a01;
        float ch1p = S1X * (a20 + a22) + (4.f - 2.f * S1X) * a21;
        float xg = (S1Y * (ch0m + ch0p) + (4.f - 2.f * S1Y) * ch0c) * 0.125f;
        float yg = S1Y * (ch1p - ch1m) * 0.125f;
        float mag = sqrtf(xg * xg + yg * yg);
        s_edge[r][c] = exp2f(0.7f * __log2f(mag));
    }
    __syncthreads();

    for (int idx = tid; idx < 38 * 34; idx += 256) {
        int r = idx / 34, c = idx % 34;
        int gc = bx0 - 1 + c;
        int l0 = min(max(gc - 2, 0), WH - 1) - (bx0 - 3);
        int l1 = min(max(gc - 1, 0), WH - 1) - (bx0 - 3);
        int l2 = min(max(gc,     0), WH - 1) - (bx0 - 3);
        int l3 = min(max(gc + 1, 0), WH - 1) - (bx0 - 3);
        int l4 = min(max(gc + 2, 0), WH - 1) - (bx0 - 3);
        s_bh[r][c] = c_gw[0] * s_edge[r][l2]
                   + c_gw[1] * (s_edge[r][l1] + s_edge[r][l3])
                   + c_gw[2] * (s_edge[r][l0] + s_edge[r][l4]);
    }
    __syncthreads();

    for (int idx = tid; idx < 34 * 34; idx += 256) {
        int r = idx / 34, c = idx % 34;
        int gr = by0 - 1 + r;
        int l0 = min(max(gr - 2, 0), HH - 1) - (by0 - 3);
        int l1 = min(max(gr - 1, 0), HH - 1) - (by0 - 3);
        int l2 = min(max(gr,     0), HH - 1) - (by0 - 3);
        int l3 = min(max(gr + 1, 0), HH - 1) - (by0 - 3);
        int l4 = min(max(gr + 2, 0), HH - 1) - (by0 - 3);
        s_bv[r][c] = c_gw[0] * s_bh[l2][c]
                   + c_gw[1] * (s_bh[l1][c] + s_bh[l3][c])
                   + c_gw[2] * (s_bh[l0][c] + s_bh[l4][c]);
    }
    __syncthreads();

    for (int idx = tid; idx < 32 * 32; idx += 256) {
        int r = idx >> 5, c = idx & 31;
        int gr = by0 + r, gc = bx0 + c;
        if (gr >= HH || gc >= WH) continue;
        int r0 = min(max(gr - 1, 0), HH - 1) - (by0 - 1);
        int r1 = gr - (by0 - 1);
        int r2 = min(gr + 1, HH - 1) - (by0 - 1);
        int c0 = min(max(gc - 1, 0), WH - 1) - (bx0 - 1);
        int c1 = gc - (bx0 - 1);
        int c2 = min(gc + 1, WH - 1) - (bx0 - 1);
        float a00 = s_bv[r0][c0], a01 = s_bv[r0][c1], a02 = s_bv[r0][c2];
        float a10 = s_bv[r1][c0], a12 = s_bv[r1][c2];
        float a20 = s_bv[r2][c0], a21 = s_bv[r2][c1], a22 = s_bv[r2][c2];
        float ch0m = S2X * (a02 - a00);
        float ch0c = S2X * (a12 - a10);
        float ch0p = S2X * (a22 - a20);
        float ch1m = S2X * (a00 + a02) + (4.f - 2.f * S2X) * a01;
        float ch1p = S2X * (a20 + a22) + (4.f - 2.f * S2X) * a21;
        float2 gv;
        gv.x = (S2Y * (ch0m + ch0p) + (4.f - 2.f * S2Y) * ch0c) * 0.125f;
        gv.y = S2Y * (ch1p - ch1m) * 0.125f;
        g_gradh[((size_t)b * HH + gr) * WH + gc] = gv;
    }
}

// ---------------------------------------------------------------------------
// Kernel 3: warp with SMEM field tile; interior blocks skip all clamps
// ---------------------------------------------------------------------------
__global__ void __launch_bounds__(256) k_warp(const float* __restrict__ img,
                                              float* __restrict__ out) {
    __shared__ float2 sF[10][35];
    int bx0 = blockIdx.x * 32, by0 = blockIdx.y * 8, b = blockIdx.z;
    int tid = threadIdx.y * 32 + threadIdx.x;

    const float2* __restrict__ G = g_gradh + (size_t)b * HH * WH;

    for (int idx = tid; idx < 34 * 10; idx += 256) {
        int ly = idx / 34, lx = idx % 34;
        int gx = min(max(bx0 - 1 + lx, 0), WF - 1);
        int gy = min(max(by0 - 1 + ly, 0), HF - 1);
        float y = fminf((float)gy * ((float)(HH - 1) / (float)(HF - 1)), (float)(HH - 1));
        float x = fminf((float)gx * ((float)(WH - 1) / (float)(WF - 1)), (float)(WH - 1));
        int y0 = (int)y, x0 = (int)x;
        int y1 = min(y0 + 1, HH - 1), x1 = min(x0 + 1, WH - 1);
        float wy = y - (float)y0, wx = x - (float)x0;
        float2 v00 = __ldg(&G[y0 * WH + x0]), v01 = __ldg(&G[y0 * WH + x1]);
        float2 v10 = __ldg(&G[y1 * WH + x0]), v11 = __ldg(&G[y1 * WH + x1]);
        float2 v;
        v.x = (v00.x * (1.f - wx) + v01.x * wx) * (1.f - wy)
            + (v10.x * (1.f - wx) + v11.x * wx) * wy;
        v.y = (v00.y * (1.f - wx) + v01.y * wx) * (1.f - wy)
            + (v10.y * (1.f - wx) + v11.y * wx) * wy;
        sF[ly][lx] = v;
    }
    __syncthreads();

    int j = bx0 + threadIdx.x;
    int i = by0 + threadIdx.y;

    const float stepx = 0.1f * (float)(WF - 1) / (float)WF;
    const float stepy = 0.1f * (float)(HF - 1) / (float)HF;
    const float ox = (float)(bx0 - 1), oy = (float)(by0 - 1);

    float px = (float)j, py = (float)i;

    bool interior = (bx0 >= 32) && (by0 >= 8) && (bx0 + 32 <= WF - 32) && (by0 + 8 <= HF - 8);

    const float* base  = img + (size_t)b * CC * HF * WF;
    float*       obase = out + (size_t)b * CC * HF * WF;

    if (interior) {
        #pragma unroll
        for (int it = 0; it < 6; ++it) {
            float lx = px - ox, ly = py - oy;
            int x0 = (int)lx, y0 = (int)ly;
            float wx = lx - (float)x0, wy = ly - (float)y0;
            float2 v00 = sF[y0][x0],     v01 = sF[y0][x0 + 1];
            float2 v10 = sF[y0 + 1][x0], v11 = sF[y0 + 1][x0 + 1];
            float tx = fmaf(wx, v01.x - v00.x, v00.x);
            float bx = fmaf(wx, v11.x - v10.x, v10.x);
            float dx = fmaf(wy, bx - tx, tx);
            float ty = fmaf(wx, v01.y - v00.y, v00.y);
            float by = fmaf(wx, v11.y - v10.y, v10.y);
            float dy = fmaf(wy, by - ty, ty);
            float len = sqrtf(fmaf(dx, dx, dy * dy)) + 0.01f;
            float inv = __fdividef(1.f, len);
            px = fmaf(-dx * stepx, inv, px);
            py = fmaf(-dy * stepy, inv, py);
        }
        int x0 = (int)px, y0 = (int)py;
        float wx = px - (float)x0, wy = py - (float)y0;
        float w00 = (1.f - wx) * (1.f - wy), w01 = wx * (1.f - wy);
        float w10 = (1.f - wx) * wy,         w11 = wx * wy;
        #pragma unroll
        for (int c = 0; c < CC; ++c) {
            const float* p = base + (size_t)c * HF * WF;
            float v = w00 * p[y0 * WF + x0] + w01 * p[y0 * WF + x0 + 1]
                    + w10 * p[(y0 + 1) * WF + x0] + w11 * p[(y0 + 1) * WF + x0 + 1];
            obase[(size_t)c * HF * WF + (size_t)i * WF + j] = fminf(fmaxf(v, 0.f), 1.f);
        }
    } else {
        #pragma unroll
        for (int it = 0; it < 6; ++it) {
            float cx = fminf(fmaxf(px, 0.f), (float)(WF - 1));
            float cy = fminf(fmaxf(py, 0.f), (float)(HF - 1));
            float lx = cx - ox, ly = cy - oy;
            int x0 = (int)lx, y0 = (int)ly;
            float wx = lx - (float)x0, wy = ly - (float)y0;
            float2 v00 = sF[y0][x0],     v01 = sF[y0][x0 + 1];
            float2 v10 = sF[y0 + 1][x0], v11 = sF[y0 + 1][x0 + 1];
            float tx = fmaf(wx, v01.x - v00.x, v00.x);
            float bx = fmaf(wx, v11.x - v10.x, v10.x);
            float dx = fmaf(wy, bx - tx, tx);
            float ty = fmaf(wx, v01.y - v00.y, v00.y);
            float by = fmaf(wx, v11.y - v10.y, v10.y);
            float dy = fmaf(wy, by - ty, ty);
            float len = sqrtf(fmaf(dx, dx, dy * dy)) + 0.01f;
            float inv = __fdividef(1.f, len);
            px = fmaf(-dx * stepx, inv, px);
            py = fmaf(-dy * stepy, inv, py);
        }
        float cx = fminf(fmaxf(px, 0.f), (float)(WF - 1));
        float cy = fminf(fmaxf(py, 0.f), (float)(HF - 1));
        int x0 = (int)cx, y0 = (int)cy;
        int x1 = min(x0 + 1, WF - 1), y1 = min(y0 + 1, HF - 1);
        float wx = cx - (float)x0, wy = cy - (float)y0;
        float w00 = (1.f - wx) * (1.f - wy), w01 = wx * (1.f - wy);
        float w10 = (1.f - wx) * wy,         w11 = wx * wy;
        #pragma unroll
        for (int c = 0; c < CC; ++c) {
            const float* p = base + (size_t)c * HF * WF;
            float v = w00 * p[y0 * WF + x0] + w01 * p[y0 * WF + x1]
                    + w10 * p[y1 * WF + x0] + w11 * p[y1 * WF + x1];
            obase[(size_t)c * HF * WF + (size_t)i * WF + j] = fminf(fmaxf(v, 0.f), 1.f);
        }
    }
}

// ---------------------------------------------------------------------------
extern "C" void kernel_launch(void* const* d_in, const int* in_sizes, int n_in,
                              void* d_out, int out_size) {
    const float* img = (const float*)d_in[0];
    float* out = (float*)d_out;

    dim3 grid_l((WH / 2 + 255) / 256, HH, BB);
    dim3 grid_t((WH + 31) / 32, (HH + 31) / 32, BB);
    dim3 grid_w(WF / 32, HF / 8, BB);

    k_luma_down<<<grid_l, 256>>>(img);
    k_field    <<<grid_t, 256>>>();
    k_warp     <<<grid_w, dim3(32, 8)>>>(img, out);
}